// round 5
// baseline (speedup 1.0000x reference)
#include <cuda_runtime.h>
#include <cuda_bf16.h>

// FineMatching (P=512, R=S=128, K=3, THRESH=0.05, OR-combine, conditional scale).
//   e = exp(x); rowT[r]/colT[s] = 3rd-largest of row/col
//   score = 0.5*ncs[p]*e*((e>=rowT)+(e>=colT))
//   corr  = ((e>=rowT)|(e>=colT)) & (e>0.05) & refm[r] & srcm[s]
//
// R5: latency-chain attack. P2 uses 4 independent interleaved top-3
// accumulators per thread (4x shorter RAW chain, LDS fully pipelined).
// rowT+refmask fused to float2 (one LDS.64 in P3). P1 2-deep prefetch.
// Smem stride 132 floats; all phases bank-conflict-free (halves +16 banks).

#define PP 512
#define NT 512
#define THRESH 0.05f

struct Top3 { float v1, v2, v3; };

__device__ __forceinline__ void ins3(Top3& t, float v) {
    float t1 = fminf(t.v1, v);
    float t2 = fminf(t.v2, v);
    t.v1 = fmaxf(t.v1, v);
    t.v2 = fmaxf(t.v2, t1);
    t.v3 = fmaxf(t.v3, t2);
}

__device__ __forceinline__ void merge(Top3& a, const Top3& b) {
    ins3(a, b.v1);
    ins3(a, b.v2);
    ins3(a, b.v3);
}

__device__ __forceinline__ void merge_xor1(Top3& t) {
    Top3 b;
    b.v1 = __shfl_xor_sync(0xffffffffu, t.v1, 1);
    b.v2 = __shfl_xor_sync(0xffffffffu, t.v2, 1);
    b.v3 = __shfl_xor_sync(0xffffffffu, t.v3, 1);
    merge(t, b);
}

#define T3INIT {-1e30f, -1e30f, -1e30f}

__global__ __launch_bounds__(NT, 3) void fine_matching_kernel(
    const float4* __restrict__ msm4,        // [P,R,S] as float4
    const unsigned int* __restrict__ refm,  // [P,R] 32-bit bool
    const uint4* __restrict__ srcm4,        // [P,S] 32-bit bool as uint4
    const float* __restrict__ ncs,          // [P]
    float4* __restrict__ out4,              // [score | corr] as float4
    int write_corr)
{
    extern __shared__ float4 sh4[];
    float* e        = (float*)sh4;                  // [128*132]
    float2* rowInfo = (float2*)(e + 128 * 132);     // [128] (rowT, refmaskF)
    float* colT     = (float*)(rowInfo + 128);      // [128]

    const int p    = blockIdx.x;
    const int tid  = threadIdx.x;
    const int lane = tid & 31;

    // ---- Phase 0/1: ref-mask -> rowInfo.y; load + exp tile (2-deep prefetch)
    if (tid < 128) rowInfo[tid].y = (refm[p * 128 + tid] != 0u) ? 1.0f : 0.0f;

    {
        const float4* g = msm4 + p * 4096 + tid;
        float4* sp = sh4 + (tid >> 5) * 33 + lane;
        float4 cur = g[0];
        #pragma unroll
        for (int k = 0; k < 8; k++) {
            float4 nxt;
            if (k < 7) nxt = g[(k + 1) * NT];
            sp[k * 16 * 33] = make_float4(__expf(cur.x), __expf(cur.y),
                                          __expf(cur.z), __expf(cur.w));
            cur = nxt;
        }
    }
    __syncthreads();

    // ---- Phase 2: top-3 thresholds, 4 interleaved accumulators per thread
    if (tid < 256) {
        // columns: 2 threads/col; half1 scans rows 68..127 then 64..67
        const int s    = tid >> 1;
        const int half = tid & 1;
        Top3 t0 = T3INIT, t1 = T3INIT, t2 = T3INIT, t3 = T3INIT;
        const float* pa = e + (half ? 68 * 132 : 0) + s;
        #pragma unroll
        for (int j = 0; j < 15; j++) {
            ins3(t0, pa[(4 * j + 0) * 132]);
            ins3(t1, pa[(4 * j + 1) * 132]);
            ins3(t2, pa[(4 * j + 2) * 132]);
            ins3(t3, pa[(4 * j + 3) * 132]);
        }
        const float* pb = e + (half ? 64 * 132 : 60 * 132) + s;
        ins3(t0, pb[0 * 132]);
        ins3(t1, pb[1 * 132]);
        ins3(t2, pb[2 * 132]);
        ins3(t3, pb[3 * 132]);
        merge(t0, t1);
        merge(t2, t3);
        merge(t0, t2);
        merge_xor1(t0);
        if (!half) colT[s] = t0.v3;
    } else {
        // rows: 2 threads/row via LDS.128; half1 reads f4 20..31 then 16..19
        const int u    = tid - 256;
        const int r    = u >> 1;
        const int half = u & 1;
        Top3 t0 = T3INIT, t1 = T3INIT, t2 = T3INIT, t3 = T3INIT;
        const float4* ra = sh4 + r * 33 + (half ? 20 : 0);
        #pragma unroll
        for (int j = 0; j < 12; j++) {
            float4 v = ra[j];
            ins3(t0, v.x);
            ins3(t1, v.y);
            ins3(t2, v.z);
            ins3(t3, v.w);
        }
        const float4* rb = sh4 + r * 33 + (half ? 16 : 12);
        #pragma unroll
        for (int j = 0; j < 4; j++) {
            float4 v = rb[j];
            ins3(t0, v.x);
            ins3(t1, v.y);
            ins3(t2, v.z);
            ins3(t3, v.w);
        }
        merge(t0, t1);
        merge(t2, t3);
        merge(t0, t2);
        merge_xor1(t0);
        if (!half) rowInfo[r].x = t0.v3;
    }
    __syncthreads();

    // ---- Phase 3: dense output (LDS.64 + LDS.128 + 2x STG.128 per iter)
    const float scale = 0.5f * __ldg(ncs + p);
    const float4 cT = *(const float4*)(colT + 4 * lane);
    const uint4 smv = srcm4[p * 32 + lane];
    const float m0 = (smv.x != 0u) ? 1.f : 0.f;
    const float m1 = (smv.y != 0u) ? 1.f : 0.f;
    const float m2 = (smv.z != 0u) ? 1.f : 0.f;
    const float m3 = (smv.w != 0u) ? 1.f : 0.f;

    const float4* tp  = sh4 + (tid >> 5) * 33 + lane;
    const float2* rip = rowInfo + (tid >> 5);
    float4* sco = out4 + (size_t)p * 4096 + tid;
    float4* cor = sco + (size_t)PP * 4096;

    if (write_corr) {
        #pragma unroll
        for (int k = 0; k < 8; k++) {
            float2 ri = rip[16 * k];        // (rowT, refmaskF)
            float4 v  = tp[k * 16 * 33];

            bool ax = v.x >= ri.x, bx = v.x >= cT.x;
            bool ay = v.y >= ri.x, by = v.y >= cT.y;
            bool az = v.z >= ri.x, bz = v.z >= cT.z;
            bool aw = v.w >= ri.x, bw = v.w >= cT.w;

            float svx = scale * v.x, svy = scale * v.y;
            float svz = scale * v.z, svw = scale * v.w;

            float4 s4;
            s4.x = (ax ? svx : 0.f) + (bx ? svx : 0.f);
            s4.y = (ay ? svy : 0.f) + (by ? svy : 0.f);
            s4.z = (az ? svz : 0.f) + (bz ? svz : 0.f);
            s4.w = (aw ? svw : 0.f) + (bw ? svw : 0.f);
            __stcs(sco + k * NT, s4);

            float4 c4;
            c4.x = ((ax || bx) && v.x > THRESH) ? ri.y * m0 : 0.f;
            c4.y = ((ay || by) && v.y > THRESH) ? ri.y * m1 : 0.f;
            c4.z = ((az || bz) && v.z > THRESH) ? ri.y * m2 : 0.f;
            c4.w = ((aw || bw) && v.w > THRESH) ? ri.y * m3 : 0.f;
            __stcs(cor + k * NT, c4);
        }
    } else {
        #pragma unroll
        for (int k = 0; k < 8; k++) {
            float2 ri = rip[16 * k];
            float4 v  = tp[k * 16 * 33];
            bool ax = v.x >= ri.x, bx = v.x >= cT.x;
            bool ay = v.y >= ri.x, by = v.y >= cT.y;
            bool az = v.z >= ri.x, bz = v.z >= cT.z;
            bool aw = v.w >= ri.x, bw = v.w >= cT.w;
            float svx = scale * v.x, svy = scale * v.y;
            float svz = scale * v.z, svw = scale * v.w;
            float4 s4;
            s4.x = (ax ? svx : 0.f) + (bx ? svx : 0.f);
            s4.y = (ay ? svy : 0.f) + (by ? svy : 0.f);
            s4.z = (az ? svz : 0.f) + (bz ? svz : 0.f);
            s4.w = (aw ? svw : 0.f) + (bw ? svw : 0.f);
            __stcs(sco + k * NT, s4);
        }
    }
}

extern "C" void kernel_launch(void* const* d_in, const int* in_sizes, int n_in,
                              void* d_out, int out_size) {
    const float4* msm4       = (const float4*)d_in[0];
    const unsigned int* refm = (const unsigned int*)d_in[1];
    const uint4* srcm4       = (const uint4*)d_in[2];
    const float* ncs         = (const float*)d_in[3];
    float4* out4             = (float4*)d_out;

    const int prs = PP * 128 * 128;
    int write_corr = (out_size >= 2 * prs) ? 1 : 0;

    // tile 128*132 floats + rowInfo(float2[128]) + colT(float[128])
    size_t smem = (size_t)(128 * 132) * sizeof(float)
                + 128 * sizeof(float2) + 128 * sizeof(float);   // ~69KB
    cudaFuncSetAttribute(fine_matching_kernel,
                         cudaFuncAttributeMaxDynamicSharedMemorySize, (int)smem);

    fine_matching_kernel<<<PP, NT, smem>>>(msm4, refm, srcm4, ncs, out4,
                                           write_corr);
}